// round 6
// baseline (speedup 1.0000x reference)
#include <cuda_runtime.h>
#include <math.h>

// ---------------------------------------------------------------------------
// SparseMoE: top-2 of 8 experts, T=4096 tokens, H=2048, I=8192, fp32.
// Pipeline (all launches graph-capturable, default stream):
//   zero -> router (logits + top2 + counts) -> offsets -> assign ->
//   grouped GEMM1 (gather x, GELU) -> grouped GEMM2 (x weight) -> combine.
// d_out layout assumed: [out (T*H) | router_logits (T*E)], both f32.
// ---------------------------------------------------------------------------

#define HDIM 2048
#define IDIM 8192
#define NEXP 8
#define NTOK 4096
#define NPAIR (NTOK * 2)        // 8192 (token, expert) pairs

#define BM 128
#define BN 128
#define BK 16

// -------------------- device scratch (static globals only) -----------------
__device__ int   g_count[NEXP];
__device__ int   g_off[NEXP];
__device__ int   g_cursor[NEXP];
__device__ int   g_topk_e[NPAIR];
__device__ float g_topk_w[NPAIR];
__device__ int   g_rowtok[NPAIR];     // permuted pair -> token
__device__ float g_roww[NPAIR];       // permuted pair -> routing weight
__device__ int   g_pairpos[NPAIR];    // token,k -> permuted row
__device__ float g_hmid[(size_t)NPAIR * IDIM];   // 268 MB
__device__ float g_ypart[(size_t)NPAIR * HDIM];  // 67 MB

// -------------------- f32x2 packed-FMA helpers -----------------------------
__device__ __forceinline__ unsigned long long pack2(float lo, float hi) {
    unsigned long long r;
    asm("mov.b64 %0, {%1, %2};" : "=l"(r) : "f"(lo), "f"(hi));
    return r;
}
__device__ __forceinline__ void unpack2(unsigned long long v, float &lo, float &hi) {
    asm("mov.b64 {%0, %1}, %2;" : "=f"(lo), "=f"(hi) : "l"(v));
}
__device__ __forceinline__ void ffma2(unsigned long long &c,
                                      unsigned long long a,
                                      unsigned long long b) {
    asm("fma.rn.f32x2 %0, %1, %2, %3;" : "=l"(c) : "l"(a), "l"(b), "l"(c));
}

// -------------------- K0: zero counts / cursors ----------------------------
__global__ void zero_kernel() {
    int t = threadIdx.x;
    if (t < NEXP) { g_count[t] = 0; g_cursor[t] = 0; }
}

// -------------------- K1: router (one warp per token) ----------------------
__global__ void router_kernel(const float* __restrict__ x,
                              const float* __restrict__ gw,
                              float* __restrict__ logits_out) {
    int warp = (blockIdx.x * blockDim.x + threadIdx.x) >> 5;
    int lane = threadIdx.x & 31;
    if (warp >= NTOK) return;
    const float* xr = x + (size_t)warp * HDIM;

    float acc[NEXP];
#pragma unroll
    for (int e = 0; e < NEXP; ++e) acc[e] = 0.f;

    for (int h = lane; h < HDIM; h += 32) {
        float xv = xr[h];
        float4 g0 = *(const float4*)(gw + (size_t)h * NEXP);
        float4 g1 = *(const float4*)(gw + (size_t)h * NEXP + 4);
        acc[0] += xv * g0.x; acc[1] += xv * g0.y;
        acc[2] += xv * g0.z; acc[3] += xv * g0.w;
        acc[4] += xv * g1.x; acc[5] += xv * g1.y;
        acc[6] += xv * g1.z; acc[7] += xv * g1.w;
    }
#pragma unroll
    for (int e = 0; e < NEXP; ++e)
#pragma unroll
        for (int o = 16; o > 0; o >>= 1)
            acc[e] += __shfl_xor_sync(0xffffffffu, acc[e], o);

    if (lane == 0) {
        *(float4*)(logits_out + (size_t)warp * NEXP) =
            make_float4(acc[0], acc[1], acc[2], acc[3]);
        *(float4*)(logits_out + (size_t)warp * NEXP + 4) =
            make_float4(acc[4], acc[5], acc[6], acc[7]);

        int i0 = 0;
#pragma unroll
        for (int e = 1; e < NEXP; ++e) if (acc[e] > acc[i0]) i0 = e;
        int i1 = (i0 == 0) ? 1 : 0;
#pragma unroll
        for (int e = 0; e < NEXP; ++e)
            if (e != i0 && acc[e] > acc[i1]) i1 = e;

        float m  = fmaxf(acc[i0], acc[i1]);
        float e0 = expf(acc[i0] - m);
        float e1 = expf(acc[i1] - m);
        float inv = 1.f / (e0 + e1);

        g_topk_e[warp * 2]     = i0;
        g_topk_e[warp * 2 + 1] = i1;
        g_topk_w[warp * 2]     = e0 * inv;
        g_topk_w[warp * 2 + 1] = e1 * inv;
        atomicAdd(&g_count[i0], 1);
        atomicAdd(&g_count[i1], 1);
    }
}

// -------------------- K2: prefix offsets -----------------------------------
__global__ void offsets_kernel() {
    if (threadIdx.x == 0) {
        int s = 0;
#pragma unroll
        for (int e = 0; e < NEXP; ++e) { g_off[e] = s; s += g_count[e]; }
    }
}

// -------------------- K3: slot assignment ----------------------------------
__global__ void assign_kernel() {
    int t = blockIdx.x * blockDim.x + threadIdx.x;
    if (t >= NTOK) return;
#pragma unroll
    for (int k = 0; k < 2; ++k) {
        int e = g_topk_e[t * 2 + k];
        int slot = atomicAdd(&g_cursor[e], 1);
        int row = g_off[e] + slot;
        g_rowtok[row] = t;
        g_roww[row]   = g_topk_w[t * 2 + k];
        g_pairpos[t * 2 + k] = row;
    }
}

// -------------------- K4: GEMM1  hmid = gelu(x_gather @ w_in[e]) ----------
__global__ __launch_bounds__(256, 2)
void gemm1_kernel(const float* __restrict__ x, const float* __restrict__ w_in) {
    const int e   = blockIdx.x >> 5;
    const int tm  = blockIdx.x & 31;
    const int cnt = g_count[e];
    if (tm * BM >= cnt) return;
    const int tn   = blockIdx.y;
    const int row0 = g_off[e] + tm * BM;
    const float* Bb = w_in + (size_t)e * HDIM * IDIM + (size_t)tn * BN;

    __shared__ float As[2][BK][BM];
    __shared__ float Bs[2][BK][BN];

    const int tid = threadIdx.x;
    // A loader: thread -> (m = tid&127, k-quad = (tid>>7)*8)
    const int am  = tid & 127;
    const int akq = (tid >> 7) << 3;
    const int inrow  = tm * BM + am;
    const bool avalid = inrow < cnt;
    const int tok = avalid ? g_rowtok[row0 + am] : 0;
    const float* Ap = x + (size_t)tok * HDIM + akq;
    // B loader: thread -> (k = tid>>4, n8 = (tid&15)*8)
    const int bk = tid >> 4;
    const int bn = (tid & 15) << 3;
    const float* Bp = Bb + (size_t)bk * IDIM + bn;
    // compute mapping: 8x8 microtile
    const int m0 = (tid >> 4) << 3;
    const int n0 = (tid & 15) << 3;

    unsigned long long acc[8][4];
#pragma unroll
    for (int i = 0; i < 8; ++i)
#pragma unroll
        for (int j = 0; j < 4; ++j) acc[i][j] = 0ull;

    { // prologue tile 0
        float4 a0 = *(const float4*)(Ap);
        float4 a1 = *(const float4*)(Ap + 4);
        As[0][akq + 0][am] = a0.x; As[0][akq + 1][am] = a0.y;
        As[0][akq + 2][am] = a0.z; As[0][akq + 3][am] = a0.w;
        As[0][akq + 4][am] = a1.x; As[0][akq + 5][am] = a1.y;
        As[0][akq + 6][am] = a1.z; As[0][akq + 7][am] = a1.w;
        *(float4*)&Bs[0][bk][bn]     = *(const float4*)(Bp);
        *(float4*)&Bs[0][bk][bn + 4] = *(const float4*)(Bp + 4);
    }
    __syncthreads();

    int buf = 0;
    const int KT = HDIM / BK;
    for (int kt = 0; kt < KT; ++kt) {
        float4 na0, na1, nb0, nb1;
        if (kt + 1 < KT) {
            int k0 = (kt + 1) * BK;
            na0 = *(const float4*)(Ap + k0);
            na1 = *(const float4*)(Ap + k0 + 4);
            nb0 = *(const float4*)(Bp + (size_t)k0 * IDIM);
            nb1 = *(const float4*)(Bp + (size_t)k0 * IDIM + 4);
        }
#pragma unroll
        for (int kk = 0; kk < BK; ++kk) {
            float a8[8];
            *(float4*)&a8[0] = *(const float4*)&As[buf][kk][m0];
            *(float4*)&a8[4] = *(const float4*)&As[buf][kk][m0 + 4];
            ulonglong2 bb0 = *(const ulonglong2*)&Bs[buf][kk][n0];
            ulonglong2 bb1 = *(const ulonglong2*)&Bs[buf][kk][n0 + 4];
            unsigned long long b2[4] = {bb0.x, bb0.y, bb1.x, bb1.y};
#pragma unroll
            for (int i = 0; i < 8; ++i) {
                unsigned long long a2 = pack2(a8[i], a8[i]);
#pragma unroll
                for (int j = 0; j < 4; ++j) ffma2(acc[i][j], a2, b2[j]);
            }
        }
        if (kt + 1 < KT) {
            int nb2 = buf ^ 1;
            As[nb2][akq + 0][am] = na0.x; As[nb2][akq + 1][am] = na0.y;
            As[nb2][akq + 2][am] = na0.z; As[nb2][akq + 3][am] = na0.w;
            As[nb2][akq + 4][am] = na1.x; As[nb2][akq + 5][am] = na1.y;
            As[nb2][akq + 6][am] = na1.z; As[nb2][akq + 7][am] = na1.w;
            *(float4*)&Bs[nb2][bk][bn]     = nb0;
            *(float4*)&Bs[nb2][bk][bn + 4] = nb1;
            __syncthreads();
            buf = nb2;
        }
    }

    // epilogue: exact GELU, store to g_hmid
#pragma unroll
    for (int i = 0; i < 8; ++i) {
        int r = tm * BM + m0 + i;
        if (r < cnt) {
            float v[8];
#pragma unroll
            for (int j = 0; j < 4; ++j) unpack2(acc[i][j], v[2 * j], v[2 * j + 1]);
#pragma unroll
            for (int k = 0; k < 8; ++k) {
                float t = v[k];
                v[k] = 0.5f * t * (1.0f + erff(t * 0.7071067811865476f));
            }
            float* dst = g_hmid + (size_t)(row0 + m0 + i) * IDIM
                       + (size_t)tn * BN + n0;
            *(float4*)(dst)     = make_float4(v[0], v[1], v[2], v[3]);
            *(float4*)(dst + 4) = make_float4(v[4], v[5], v[6], v[7]);
        }
    }
}

// -------------------- K5: GEMM2  ypart = w * (hmid @ w_out[e]) -------------
__global__ __launch_bounds__(256, 2)
void gemm2_kernel(const float* __restrict__ w_out) {
    const int e   = blockIdx.x >> 5;
    const int tm  = blockIdx.x & 31;
    const int cnt = g_count[e];
    if (tm * BM >= cnt) return;
    const int tn   = blockIdx.y;
    const int row0 = g_off[e] + tm * BM;
    const float* Bb = w_out + (size_t)e * IDIM * HDIM + (size_t)tn * BN;

    __shared__ float As[2][BK][BM];
    __shared__ float Bs[2][BK][BN];

    const int tid = threadIdx.x;
    const int am  = tid & 127;
    const int akq = (tid >> 7) << 3;
    const int inrow  = tm * BM + am;
    const bool avalid = inrow < cnt;
    const int arow = avalid ? (row0 + am) : row0;
    const float* Ap = g_hmid + (size_t)arow * IDIM + akq;
    const int bk = tid >> 4;
    const int bn = (tid & 15) << 3;
    const float* Bp = Bb + (size_t)bk * HDIM + bn;
    const int m0 = (tid >> 4) << 3;
    const int n0 = (tid & 15) << 3;

    unsigned long long acc[8][4];
#pragma unroll
    for (int i = 0; i < 8; ++i)
#pragma unroll
        for (int j = 0; j < 4; ++j) acc[i][j] = 0ull;

    {
        float4 a0 = *(const float4*)(Ap);
        float4 a1 = *(const float4*)(Ap + 4);
        As[0][akq + 0][am] = a0.x; As[0][akq + 1][am] = a0.y;
        As[0][akq + 2][am] = a0.z; As[0][akq + 3][am] = a0.w;
        As[0][akq + 4][am] = a1.x; As[0][akq + 5][am] = a1.y;
        As[0][akq + 6][am] = a1.z; As[0][akq + 7][am] = a1.w;
        *(float4*)&Bs[0][bk][bn]     = *(const float4*)(Bp);
        *(float4*)&Bs[0][bk][bn + 4] = *(const float4*)(Bp + 4);
    }
    __syncthreads();

    int buf = 0;
    const int KT = IDIM / BK;
    for (int kt = 0; kt < KT; ++kt) {
        float4 na0, na1, nb0, nb1;
        if (kt + 1 < KT) {
            int k0 = (kt + 1) * BK;
            na0 = *(const float4*)(Ap + k0);
            na1 = *(const float4*)(Ap + k0 + 4);
            nb0 = *(const float4*)(Bp + (size_t)k0 * HDIM);
            nb1 = *(const float4*)(Bp + (size_t)k0 * HDIM + 4);
        }
#pragma unroll
        for (int kk = 0; kk < BK; ++kk) {
            float a8[8];
            *(float4*)&a8[0] = *(const float4*)&As[buf][kk][m0];
            *(float4*)&a8[4] = *(const float4*)&As[buf][kk][m0 + 4];
            ulonglong2 bb0 = *(const ulonglong2*)&Bs[buf][kk][n0];
            ulonglong2 bb1 = *(const ulonglong2*)&Bs[buf][kk][n0 + 4];
            unsigned long long b2[4] = {bb0.x, bb0.y, bb1.x, bb1.y};
#pragma unroll
            for (int i = 0; i < 8; ++i) {
                unsigned long long a2 = pack2(a8[i], a8[i]);
#pragma unroll
                for (int j = 0; j < 4; ++j) ffma2(acc[i][j], a2, b2[j]);
            }
        }
        if (kt + 1 < KT) {
            int nb2 = buf ^ 1;
            As[nb2][akq + 0][am] = na0.x; As[nb2][akq + 1][am] = na0.y;
            As[nb2][akq + 2][am] = na0.z; As[nb2][akq + 3][am] = na0.w;
            As[nb2][akq + 4][am] = na1.x; As[nb2][akq + 5][am] = na1.y;
            As[nb2][akq + 6][am] = na1.z; As[nb2][akq + 7][am] = na1.w;
            *(float4*)&Bs[nb2][bk][bn]     = nb0;
            *(float4*)&Bs[nb2][bk][bn + 4] = nb1;
            __syncthreads();
            buf = nb2;
        }
    }

#pragma unroll
    for (int i = 0; i < 8; ++i) {
        int r = tm * BM + m0 + i;
        if (r < cnt) {
            int grow = row0 + m0 + i;
            float w = g_roww[grow];
            float v[8];
#pragma unroll
            for (int j = 0; j < 4; ++j) unpack2(acc[i][j], v[2 * j], v[2 * j + 1]);
#pragma unroll
            for (int k = 0; k < 8; ++k) v[k] *= w;
            float* dst = g_ypart + (size_t)grow * HDIM + (size_t)tn * BN + n0;
            *(float4*)(dst)     = make_float4(v[0], v[1], v[2], v[3]);
            *(float4*)(dst + 4) = make_float4(v[4], v[5], v[6], v[7]);
        }
    }
}

// -------------------- K6: combine  out = bias + y(top1) + y(top2) ----------
__global__ void combine_kernel(const float* __restrict__ bias,
                               float* __restrict__ out) {
    int idx = blockIdx.x * blockDim.x + threadIdx.x;   // T * H/4 items
    if (idx >= NTOK * (HDIM / 4)) return;
    int t  = idx >> 9;             // H/4 = 512
    int c4 = (idx & 511) << 2;
    int p0 = g_pairpos[t * 2];
    int p1 = g_pairpos[t * 2 + 1];
    float4 bv = *(const float4*)(bias + c4);
    float4 y0 = *(const float4*)(g_ypart + (size_t)p0 * HDIM + c4);
    float4 y1 = *(const float4*)(g_ypart + (size_t)p1 * HDIM + c4);
    float4 o;
    o.x = bv.x + y0.x + y1.x;
    o.y = bv.y + y0.y + y1.y;
    o.z = bv.z + y0.z + y1.z;
    o.w = bv.w + y0.w + y1.w;
    *(float4*)(out + (size_t)t * HDIM + c4) = o;
}

// ---------------------------------------------------------------------------
extern "C" void kernel_launch(void* const* d_in, const int* in_sizes, int n_in,
                              void* d_out, int out_size) {
    const float* x     = (const float*)d_in[0];   // [2,2048,2048]
    const float* gw    = (const float*)d_in[1];   // [2048,8]
    const float* w_in  = (const float*)d_in[2];   // [8,2048,8192]
    const float* w_out = (const float*)d_in[3];   // [8,8192,2048]
    const float* bias  = (const float*)d_in[4];   // [2048]
    (void)in_sizes; (void)n_in; (void)out_size;   // top_k fixed at 2

    float* out    = (float*)d_out;
    float* logits = out + (size_t)NTOK * HDIM;

    zero_kernel<<<1, 32>>>();
    router_kernel<<<NTOK / 8, 256>>>(x, gw, logits);   // 8 warps/block
    offsets_kernel<<<1, 32>>>();
    assign_kernel<<<NTOK / 256, 256>>>();
    gemm1_kernel<<<dim3(NEXP * 32, IDIM / BN), 256>>>(x, w_in);
    gemm2_kernel<<<dim3(NEXP * 32, HDIM / BN), 256>>>(w_out);
    combine_kernel<<<(NTOK * (HDIM / 4)) / 256, 256>>>(bias, out);
}

// round 9
// speedup vs baseline: 2.8830x; 2.8830x over previous
#include <cuda_runtime.h>
#include <cuda_bf16.h>
#include <math.h>
#include <cstdint>

// ---------------------------------------------------------------------------
// SparseMoE top-2/8, T=4096, H=2048, I=8192, fp32 in/out.
// Grouped GEMMs: tcgen05 split-bf16 (hi+lo) when compiling for sm_103a
// (arch-feature macros present), FFMA2 SIMT fallback otherwise.
// d_out layout: [out (T*H) | router_logits (T*E)], f32.
// ---------------------------------------------------------------------------

#if defined(__CUDA_ARCH__) && (defined(__CUDA_ARCH_FEAT_SM103_ALL) || \
    defined(__CUDA_ARCH_SPECIFIC__) || defined(__CUDA_ARCH_FAMILY_SPECIFIC__))
#define TC_ON 1
#else
#define TC_ON 0
#endif

#define HDIM 2048
#define IDIM 8192
#define NEXP 8
#define NTOK 4096
#define NPAIR (NTOK * 2)
#define BM 128
#define BN 128

// -------------------- device scratch ---------------------------------------
__device__ int   g_count[NEXP];
__device__ int   g_off[NEXP];
__device__ int   g_cursor[NEXP];
__device__ int   g_topk_e[NPAIR];
__device__ float g_topk_w[NPAIR];
__device__ int   g_rowtok[NPAIR];
__device__ float g_roww[NPAIR];
__device__ int   g_pairpos[NPAIR];
__device__ float g_hmid[(size_t)NPAIR * IDIM];   // 268 MB
__device__ float g_ypart[(size_t)NPAIR * HDIM];  // 67 MB

// -------------------- generic helpers --------------------------------------
__device__ __forceinline__ uint32_t smem_to_u32(const void* p) {
    uint32_t a;
    asm("{ .reg .u64 t; cvta.to.shared.u64 t, %1; cvt.u32.u64 %0, t; }"
        : "=r"(a) : "l"(p));
    return a;
}
__device__ __forceinline__ unsigned sw128(unsigned off) {
    return off ^ ((off >> 3) & 0x70);
}

// fp32 -> (bf16 hi, bf16 lo) split converters
__device__ __forceinline__ void cvt4(float4 v, uint2& h, uint2& l) {
    __nv_bfloat162 h0 = __floats2bfloat162_rn(v.x, v.y);
    __nv_bfloat162 h1 = __floats2bfloat162_rn(v.z, v.w);
    float2 f0 = __bfloat1622float2(h0);
    float2 f1 = __bfloat1622float2(h1);
    __nv_bfloat162 l0 = __floats2bfloat162_rn(v.x - f0.x, v.y - f0.y);
    __nv_bfloat162 l1 = __floats2bfloat162_rn(v.z - f1.x, v.w - f1.y);
    h.x = *(unsigned*)&h0; h.y = *(unsigned*)&h1;
    l.x = *(unsigned*)&l0; l.y = *(unsigned*)&l1;
}
__device__ __forceinline__ void cvt8(const float* f, uint4& h, uint4& l) {
    unsigned hv[4], lv[4];
#pragma unroll
    for (int p = 0; p < 4; ++p) {
        float a = f[2 * p], b = f[2 * p + 1];
        __nv_bfloat162 hh = __floats2bfloat162_rn(a, b);
        float2 hf = __bfloat1622float2(hh);
        __nv_bfloat162 ll = __floats2bfloat162_rn(a - hf.x, b - hf.y);
        hv[p] = *(unsigned*)&hh; lv[p] = *(unsigned*)&ll;
    }
    h = make_uint4(hv[0], hv[1], hv[2], hv[3]);
    l = make_uint4(lv[0], lv[1], lv[2], lv[3]);
}

// f32x2 packed-FMA helpers (fallback path; non-'a' feature, always compiles)
__device__ __forceinline__ unsigned long long pack2(float lo, float hi) {
    unsigned long long r;
    asm("mov.b64 %0, {%1, %2};" : "=l"(r) : "f"(lo), "f"(hi));
    return r;
}
__device__ __forceinline__ void unpack2(unsigned long long v, float &lo, float &hi) {
    asm("mov.b64 {%0, %1}, %2;" : "=f"(lo), "=f"(hi) : "l"(v));
}
__device__ __forceinline__ void ffma2(unsigned long long &c,
                                      unsigned long long a,
                                      unsigned long long b) {
    asm("fma.rn.f32x2 %0, %1, %2, %3;" : "=l"(c) : "l"(a), "l"(b), "l"(c));
}

// -------------------- tcgen05 PTX (guarded) --------------------------------
#if TC_ON
__device__ __forceinline__ uint32_t elect_one_pred() {
    uint32_t pred;
    asm volatile(
        "{\n\t.reg .pred p;\n\t"
        "elect.sync _|p, 0xFFFFFFFF;\n\t"
        "selp.b32 %0, 1, 0, p;\n\t}"
        : "=r"(pred));
    return pred;
}

#define MBARRIER_INIT(addr, count) \
    asm volatile("mbarrier.init.shared.b64 [%0], %1;" \
                 :: "r"((uint32_t)(addr)), "r"((uint32_t)(count)) : "memory")

#define MBARRIER_WAIT_PARITY(mbar_smem_addr, phase_parity) do { \
    uint32_t _mbar = (uint32_t)(mbar_smem_addr); \
    uint32_t _parity = (uint32_t)(phase_parity); \
    uint32_t _done; \
    asm volatile( \
        "{\n\t.reg .pred p;\n\t" \
        "mbarrier.try_wait.parity.acquire.cta.shared::cta.b64 p, [%1], %2;\n\t" \
        "selp.b32 %0, 1, 0, p;\n\t}" \
        : "=r"(_done) : "r"(_mbar), "r"(_parity) : "memory"); \
    if (!_done) { \
        asm volatile( \
            "{\n\t.reg .pred P1;\n\t" \
            "WAIT_LOOP_%=:\n\t" \
            "mbarrier.try_wait.parity.acquire.cta.shared::cta.b64 P1, [%0], %1, 0x989680;\n\t" \
            "@P1 bra.uni WAIT_DONE_%=;\n\t" \
            "bra.uni WAIT_LOOP_%=;\n\t" \
            "WAIT_DONE_%=:\n\t}" \
            :: "r"(_mbar), "r"(_parity) : "memory"); \
    } \
} while (0)

#define TCGEN05_ALLOC(smem_result_addr, nCols) \
    asm volatile("tcgen05.alloc.cta_group::1.sync.aligned.shared::cta.b32 [%0], %1;" \
                 :: "r"((uint32_t)(smem_result_addr)), "r"((uint32_t)(nCols)) : "memory")
#define TCGEN05_DEALLOC(tmem_addr, nCols) \
    asm volatile("tcgen05.dealloc.cta_group::1.sync.aligned.b32 %0, %1;" \
                 :: "r"(tmem_addr), "r"((uint32_t)(nCols)))
#define TCGEN05_RELINQUISH() \
    asm volatile("tcgen05.relinquish_alloc_permit.cta_group::1.sync.aligned;")
#define TCGEN05_COMMIT(mbar) \
    asm volatile("tcgen05.commit.cta_group::1.mbarrier::arrive::one.shared::cluster.b64 [%0];" \
                 :: "r"((uint32_t)(mbar)) : "memory")
#define TCGEN05_FENCE_AFTER() \
    asm volatile("tcgen05.fence::after_thread_sync;" ::: "memory")
#define TCGEN05_FENCE_BEFORE() \
    asm volatile("tcgen05.fence::before_thread_sync;" ::: "memory")
#define TCGEN05_WAIT_LD() \
    asm volatile("tcgen05.wait::ld.sync.aligned;" ::: "memory")

#define TCGEN05_LD_32X32B_X32(r, tmem_addr) \
    asm volatile( \
        "tcgen05.ld.sync.aligned.32x32b.x32.b32 " \
        "{%0, %1, %2, %3, %4, %5, %6, %7, " \
        " %8, %9, %10, %11, %12, %13, %14, %15, " \
        " %16, %17, %18, %19, %20, %21, %22, %23, " \
        " %24, %25, %26, %27, %28, %29, %30, %31}, [%32];" \
        : "=r"((r)[0]),  "=r"((r)[1]),  "=r"((r)[2]),  "=r"((r)[3]), \
          "=r"((r)[4]),  "=r"((r)[5]),  "=r"((r)[6]),  "=r"((r)[7]), \
          "=r"((r)[8]),  "=r"((r)[9]),  "=r"((r)[10]), "=r"((r)[11]), \
          "=r"((r)[12]), "=r"((r)[13]), "=r"((r)[14]), "=r"((r)[15]), \
          "=r"((r)[16]), "=r"((r)[17]), "=r"((r)[18]), "=r"((r)[19]), \
          "=r"((r)[20]), "=r"((r)[21]), "=r"((r)[22]), "=r"((r)[23]), \
          "=r"((r)[24]), "=r"((r)[25]), "=r"((r)[26]), "=r"((r)[27]), \
          "=r"((r)[28]), "=r"((r)[29]), "=r"((r)[30]), "=r"((r)[31]) \
        : "r"(tmem_addr))

__device__ __forceinline__ void mma_ss(uint32_t d, uint64_t a, uint64_t b,
                                       uint32_t idesc, bool accum) {
    uint32_t en = accum ? 1u : 0u;
    asm volatile(
        "{\n\t.reg .pred p;\n\t"
        "setp.ne.u32 p, %5, 0;\n\t"
        "tcgen05.mma.cta_group::1.kind::f16 [%0], %1, %2, %3, {%4, %4, %4, %4}, p;\n\t}"
        :: "r"(d), "l"(a), "l"(b), "r"(idesc), "r"(0u), "r"(en)
        : "memory");
}
#endif  // TC_ON

static constexpr uint64_t SMEM_DESC_BASE_SW128 =
    (uint64_t(2) << 61) | (uint64_t(1) << 46) | (uint64_t(64) << 32) | (uint64_t(1) << 16);
#define MAKE_SMEM_DESC(base_addr) \
    (SMEM_DESC_BASE_SW128 | ((uint64_t)((base_addr) >> 4) & 0x3FFF))

// idesc: dtype=F32(1<<4), atype=BF16(1<<7), btype=BF16(1<<10), N/8<<17, M/16<<24
#define GEMM_IDESC 0x8200490u   // M=128, N=128

// -------------------- SMEM layout (tcgen05 path) ---------------------------
#define TILE_SZ   16384                   // 128 rows x 64 bf16 x 2B (SW128)
#define BUF_SZ    (4 * TILE_SZ)           // Ahi, Alo, Bhi, Blo
#define SM_AHI(b) (1024 + (b) * BUF_SZ)
#define SM_BHI(b) (SM_AHI(b) + 2 * TILE_SZ)
#define SM_STAGE  (1024 + 2 * BUF_SZ)     // fp32 staging for B transpose
#define SFP       132                     // padded row stride (floats)
#define SMEM_BYTES (SM_STAGE + 64 * SFP * 4)   // 165888 (covers both paths)

// -------------------- small kernels ----------------------------------------
__global__ void zero_kernel() {
    int t = threadIdx.x;
    if (t < NEXP) { g_count[t] = 0; g_cursor[t] = 0; }
}

__global__ void router_kernel(const float* __restrict__ x,
                              const float* __restrict__ gw,
                              float* __restrict__ logits_out) {
    int warp = (blockIdx.x * blockDim.x + threadIdx.x) >> 5;
    int lane = threadIdx.x & 31;
    if (warp >= NTOK) return;
    const float* xr = x + (size_t)warp * HDIM;

    float acc[NEXP];
#pragma unroll
    for (int e = 0; e < NEXP; ++e) acc[e] = 0.f;
    for (int h = lane; h < HDIM; h += 32) {
        float xv = xr[h];
        float4 g0 = *(const float4*)(gw + (size_t)h * NEXP);
        float4 g1 = *(const float4*)(gw + (size_t)h * NEXP + 4);
        acc[0] += xv * g0.x; acc[1] += xv * g0.y;
        acc[2] += xv * g0.z; acc[3] += xv * g0.w;
        acc[4] += xv * g1.x; acc[5] += xv * g1.y;
        acc[6] += xv * g1.z; acc[7] += xv * g1.w;
    }
#pragma unroll
    for (int e = 0; e < NEXP; ++e)
#pragma unroll
        for (int o = 16; o > 0; o >>= 1)
            acc[e] += __shfl_xor_sync(0xffffffffu, acc[e], o);

    if (lane == 0) {
        *(float4*)(logits_out + (size_t)warp * NEXP) =
            make_float4(acc[0], acc[1], acc[2], acc[3]);
        *(float4*)(logits_out + (size_t)warp * NEXP + 4) =
            make_float4(acc[4], acc[5], acc[6], acc[7]);
        int i0 = 0;
#pragma unroll
        for (int e = 1; e < NEXP; ++e) if (acc[e] > acc[i0]) i0 = e;
        int i1 = (i0 == 0) ? 1 : 0;
#pragma unroll
        for (int e = 0; e < NEXP; ++e)
            if (e != i0 && acc[e] > acc[i1]) i1 = e;
        float m  = fmaxf(acc[i0], acc[i1]);
        float e0 = expf(acc[i0] - m);
        float e1 = expf(acc[i1] - m);
        float inv = 1.f / (e0 + e1);
        g_topk_e[warp * 2]     = i0;
        g_topk_e[warp * 2 + 1] = i1;
        g_topk_w[warp * 2]     = e0 * inv;
        g_topk_w[warp * 2 + 1] = e1 * inv;
        atomicAdd(&g_count[i0], 1);
        atomicAdd(&g_count[i1], 1);
    }
}

__global__ void offsets_kernel() {
    if (threadIdx.x == 0) {
        int s = 0;
#pragma unroll
        for (int e = 0; e < NEXP; ++e) { g_off[e] = s; s += g_count[e]; }
    }
}

__global__ void assign_kernel() {
    int t = blockIdx.x * blockDim.x + threadIdx.x;
    if (t >= NTOK) return;
#pragma unroll
    for (int k = 0; k < 2; ++k) {
        int e = g_topk_e[t * 2 + k];
        int slot = atomicAdd(&g_cursor[e], 1);
        int row = g_off[e] + slot;
        g_rowtok[row] = t;
        g_roww[row]   = g_topk_w[t * 2 + k];
        g_pairpos[t * 2 + k] = row;
    }
}

// -------------------- grouped GEMM -----------------------------------------
// MODE 0: hmid = gelu(gather(x) @ w_in[e]),   K=HDIM,  out stride IDIM
// MODE 1: ypart = roww * (hmid @ w_out[e]),   K=IDIM,  out stride HDIM
// KT64 = K / 64.
template <int MODE, int KT64>
__global__ __launch_bounds__(256, 1)
void gemm_tc(const float* __restrict__ Asrc, const float* __restrict__ Bsrc) {
    const int e   = blockIdx.x >> 5;
    const int tm  = blockIdx.x & 31;
    const int cnt = g_count[e];
    if (tm * BM >= cnt) return;
    const int tn   = blockIdx.y;
    const int row0 = g_off[e] + tm * BM;
    const int ldb  = (MODE == 0) ? IDIM : HDIM;
    const int kdim = (MODE == 0) ? HDIM : IDIM;
    const float* Bbase = Bsrc + (size_t)e * kdim * ldb + (size_t)tn * BN;

    extern __shared__ char smem[];
    const int tid  = threadIdx.x;
    const int wid  = tid >> 5;
    const int lane = tid & 31;

#if TC_ON
    // ======================= tcgen05 split-bf16 path =======================
    uint32_t smem_base = smem_to_u32(smem);
    if (wid == 0) TCGEN05_ALLOC(smem_base, 128);
    if (tid == 0) {
        MBARRIER_INIT(smem_base + 16, 1);
        MBARRIER_INIT(smem_base + 24, 1);
    }
    __syncthreads();
    uint32_t tmem;
    asm volatile("ld.shared.b32 %0, [%1];" : "=r"(tmem) : "r"(smem_base));

    // loader mappings
    const int ar = tid >> 1;           // A row 0..127
    const int ah = tid & 1;            // A half-row phase
    const float* Ap;
    if (MODE == 0) {
        int tok = ((tm * BM + ar) < cnt) ? g_rowtok[row0 + ar] : g_rowtok[row0];
        Ap = Asrc + (size_t)tok * HDIM + ah * 4;
    } else {
        int arow = ((tm * BM + ar) < cnt) ? (row0 + ar) : row0;
        Ap = g_hmid + (size_t)arow * IDIM + ah * 4;
    }
    const int bkr = tid >> 2;          // B k-row 0..63
    const int bq  = tid & 3;
    const float* Bp = Bbase + (size_t)bkr * ldb + bq * 4;
    const int s2n = tid >> 1;          // stage2: N row 0..127
    const int s2k = (tid & 1) * 32;    // stage2: k segment
    float* Sf = (float*)(smem + SM_STAGE);

    auto load_block = [&](int kb, int buf) {
        // stage 1: B fp32 -> staging (coalesced); A fp32 -> hi/lo bf16 tiles
        {
            const float* bp = Bp + (size_t)(kb * 64) * ldb;
            float4 bv[8];
#pragma unroll
            for (int i = 0; i < 8; ++i) bv[i] = *(const float4*)(bp + 16 * i);
#pragma unroll
            for (int i = 0; i < 8; ++i)
                *(float4*)(Sf + bkr * SFP + bq * 4 + 16 * i) = bv[i];

            const float* ap = Ap + kb * 64;
            float4 av[8];
#pragma unroll
            for (int i = 0; i < 8; ++i) av[i] = *(const float4*)(ap + 8 * i);
            char* ahiP = smem + SM_AHI(buf);
#pragma unroll
            for (int i = 0; i < 8; ++i) {
                uint2 h2, l2;
                cvt4(av[i], h2, l2);
                unsigned so = sw128((unsigned)(ar * 128 + 16 * i)) + ah * 8;
                *(uint2*)(ahiP + so) = h2;
                *(uint2*)(ahiP + TILE_SZ + so) = l2;
            }
        }
        __syncthreads();
        // stage 2: staging -> K-major hi/lo bf16 B tiles (transpose)
        {
            char* bhiP = smem + SM_BHI(buf);
#pragma unroll
            for (int g = 0; g < 4; ++g) {
                float f[8];
#pragma unroll
                for (int j = 0; j < 8; ++j)
                    f[j] = Sf[(s2k + 8 * g + j) * SFP + s2n];
                uint4 h4, l4;
                cvt8(f, h4, l4);
                unsigned so = sw128((unsigned)(s2n * 128 + s2k * 2 + g * 16));
                *(uint4*)(bhiP + so) = h4;
                *(uint4*)(bhiP + TILE_SZ + so) = l4;
            }
        }
    };

    load_block(0, 0);
    __syncthreads();

    for (int kb = 0; kb < KT64; ++kb) {
        int buf = kb & 1;
        if (wid == 0 && elect_one_pred()) {
            asm volatile("fence.proxy.async.shared::cta;" ::: "memory");
            uint64_t dA  = MAKE_SMEM_DESC(smem_base + SM_AHI(buf));
            uint64_t dB  = MAKE_SMEM_DESC(smem_base + SM_BHI(buf));
            uint64_t dAl = dA + (TILE_SZ >> 4);
            uint64_t dBl = dB + (TILE_SZ >> 4);
#pragma unroll
            for (int s = 0; s < 4; ++s)
                mma_ss(tmem, dA + s * 2, dB + s * 2, GEMM_IDESC, !(kb == 0 && s == 0));
#pragma unroll
            for (int s = 0; s < 4; ++s)
                mma_ss(tmem, dA + s * 2, dBl + s * 2, GEMM_IDESC, true);
#pragma unroll
            for (int s = 0; s < 4; ++s)
                mma_ss(tmem, dAl + s * 2, dB + s * 2, GEMM_IDESC, true);
            TCGEN05_COMMIT(smem_base + 16 + buf * 8);
        }
        if (kb + 1 < KT64) {
            int nbuf = buf ^ 1;
            if (kb >= 1)
                MBARRIER_WAIT_PARITY(smem_base + 16 + nbuf * 8, ((kb - 1) >> 1) & 1);
            load_block(kb + 1, nbuf);
        }
        __syncthreads();
    }
    MBARRIER_WAIT_PARITY(smem_base + 16 + ((KT64 - 1) & 1) * 8, ((KT64 - 1) >> 1) & 1);
    TCGEN05_FENCE_AFTER();

    // epilogue: warps 0-3 read D (each warp = its 32-lane subpartition)
    if (wid < 4) {
        int m = wid * 32 + lane;
        bool valid = (tm * BM + m) < cnt;
        int grow = row0 + m;
        float wscale = 1.f;
        if (MODE == 1) wscale = valid ? g_roww[grow] : 0.f;
#pragma unroll
        for (int nb = 0; nb < 4; ++nb) {
            uint32_t dr[32];
            TCGEN05_LD_32X32B_X32(dr, tmem + nb * 32);
            TCGEN05_WAIT_LD();
            if (valid) {
                float f[32];
#pragma unroll
                for (int j = 0; j < 32; ++j) f[j] = __uint_as_float(dr[j]);
                if (MODE == 0) {
#pragma unroll
                    for (int j = 0; j < 32; ++j) {
                        float t = f[j];
                        f[j] = 0.5f * t * (1.0f + erff(t * 0.7071067811865476f));
                    }
                } else {
#pragma unroll
                    for (int j = 0; j < 32; ++j) f[j] *= wscale;
                }
                float* dst = (MODE == 0 ? g_hmid : g_ypart)
                           + (size_t)grow * ldb + (size_t)tn * BN + nb * 32;
#pragma unroll
                for (int q = 0; q < 8; ++q)
                    *(float4*)(dst + 4 * q) =
                        make_float4(f[4 * q], f[4 * q + 1], f[4 * q + 2], f[4 * q + 3]);
            }
        }
        TCGEN05_FENCE_BEFORE();
    }
    __syncthreads();
    if (wid == 0) {
        TCGEN05_RELINQUISH();
        TCGEN05_DEALLOC(tmem, 128);
    }

#else
    // ================= FFMA2 SIMT fallback (R5, known-passing) =============
    (void)lane; (void)wid;
    const int KT16 = KT64 * 4;         // BK = 16
    float* As = (float*)smem;                       // [2][16][128]
    float* Bs = As + 2 * 16 * 128;                  // [2][16][128]

    const int am  = tid & 127;
    const int akq = (tid >> 7) << 3;
    const bool avalid = (tm * BM + am) < cnt;
    const float* Ap;
    if (MODE == 0) {
        int tok = avalid ? g_rowtok[row0 + am] : g_rowtok[row0];
        Ap = Asrc + (size_t)tok * HDIM + akq;
    } else {
        int arow = avalid ? (row0 + am) : row0;
        Ap = g_hmid + (size_t)arow * IDIM + akq;
    }
    const int bk = tid >> 4;
    const int bn = (tid & 15) << 3;
    const float* Bp = Bbase + (size_t)bk * ldb + bn;
    const int m0 = (tid >> 4) << 3;
    const int n0 = (tid & 15) << 3;

    unsigned long long acc[8][4];
#pragma unroll
    for (int i = 0; i < 8; ++i)
#pragma unroll
        for (int j = 0; j < 4; ++j) acc[i][j] = 0ull;

    {
        float4 a0 = *(const float4*)(Ap);
        float4 a1 = *(const float4*)(Ap + 4);
        float* A0 = As;
        A0[(akq + 0) * 128 + am] = a0.x; A0[(akq + 1) * 128 + am] = a0.y;
        A0[(akq + 2) * 128 + am] = a0.z; A0[(akq + 3) * 128 + am] = a0.w;
        A0[(akq + 4) * 128 + am] = a1.x; A0[(akq + 5) * 128 + am] = a1.y;
        A0[(akq + 6) * 128 + am] = a1.z; A0[(akq + 7) * 128 + am] = a1.w;
        *(float4*)&Bs[bk * 128 + bn]     = *(const float4*)(Bp);
        *(float4*)&Bs[bk * 128 + bn + 4] = *(const float4*)(Bp + 4);
    }
    __syncthreads();

    int buf = 0;
    for (int kt = 0; kt < KT16; ++kt) {
        float4 na0, na1, nb0, nb1;
        if (kt + 1 < KT16) {
            int k0 = (kt + 1) * 16;
            na0 = *(const float4*)(Ap + k0);
            na1 = *(const float4*)(Ap + k0 + 4);
            nb0 = *(const float4*)(Bp + (size_t)k0 * ldb);
            nb1 = *(const float4*)(Bp + (size_t)k0 * ldb + 4);
        }
        const float* Ab = As + buf * 16 * 128;
        const float* Bb = Bs + buf * 16 * 128;
#pragma unroll
        for (int kk = 0; kk < 16; ++kk) {
            float a8[8];
            *(float4*)&a8[0] = *(const float4*)&Ab[kk * 128 + m0];
            *(float4*)&a8[4] = *(const float4*)&Ab[kk * 128 + m0 + 4];
            ulonglong2 bb0 = *(const ulonglong2*)&Bb[kk * 128 + n0];
            ulonglong2 bb1 = *(const ulonglong2*)&Bb[kk * 128 + n0 + 4];
            unsigned long long b2[4] = {bb0.x, bb0.y, bb1.x, bb1.y};
#pragma unroll
            for (int i = 0; i < 8; ++i) {
                unsigned long long a2 = pack2(a8[i], a8[i]);
#pragma unroll
                for (int j = 0; j < 4; ++j) ffma2(acc[i][j], a2, b2[j]);
            }
        }
        if (kt + 1 < KT16) {
            int nb2 = buf ^ 1;
            float* An = As + nb2 * 16 * 128;
            An[(akq + 0) * 128 + am] = na0.x; An[(akq + 1) * 128 + am] = na0.y;
            An[(akq + 2) * 128 + am] = na0.z; An[(akq + 3) * 128 + am] = na0.w;
            An[(akq + 4) * 128 + am] = na1.x; An[(akq + 5) * 128 + am] = na1.y;
            An[(akq + 6) * 128 + am] = na1.z; An[(akq + 7) * 128 + am] = na1.w;
            float* Bn = Bs + nb2 * 16 * 128;
            *(float4*)&Bn[bk * 128 + bn]     = nb0;
            *(float4*)&Bn[bk * 128 + bn + 4] = nb1;
            __syncthreads();
            buf = nb2;
        }
    }

#pragma unroll
    for (int i = 0; i < 8; ++i) {
        int r = tm * BM + m0 + i;
        if (r < cnt) {
            int grow = row0 + m0 + i;
            float v[8];
#pragma unroll
            for (int j = 0; j < 4; ++j) unpack2(acc[i][j], v[2 * j], v[2 * j + 1]);
            if (MODE == 0) {
#pragma unroll
                for (int k = 0; k < 8; ++k) {
                    float t = v[k];
                    v[k] = 0.5f * t * (1.0f + erff(t * 0.7071067811865476f));
                }
            } else {
                float w = g_roww[grow];
#pragma unroll
                for (int k = 0; k < 8; ++k) v[k] *= w;
            }
            float* dst = (MODE == 0 ? g_hmid : g_ypart)
                       + (size_t)grow * ldb + (size_t)tn * BN + n0;
            *(float4*)(dst)     = make_float4(v[0], v[1], v[2], v[3]);
            *(float4*)(dst + 4) = make_float4(v[4], v[5], v[6], v[7]);
        }
    }
#endif  // TC_ON
}

// -------------------- combine ----------------------------------------------
__global__ void combine_kernel(const float* __restrict__ bias,
                               float* __restrict__ out) {
    int idx = blockIdx.x * blockDim.x + threadIdx.x;
    if (idx >= NTOK * (HDIM / 4)) return;
    int t  = idx >> 9;
    int c4 = (idx & 511) << 2;
    int p0 = g_pairpos[t * 2];
    int p1 = g_pairpos[t * 2 + 1];
    float4 bv = *(const float4*)(bias + c4);
    float4 y0 = *(const float4*)(g_ypart + (size_t)p0 * HDIM + c4);
    float4 y1 = *(const float4*)(g_ypart + (size_t)p1 * HDIM + c4);
    float4 o;
    o.x = bv.x + y0.x + y1.x;
    o.y = bv.y + y0.y + y1.y;
    o.z = bv.z + y0.z + y1.z;
    o.w = bv.w + y0.w + y1.w;
    *(float4*)(out + (size_t)t * HDIM + c4) = o;
}

// ---------------------------------------------------------------------------
extern "C" void kernel_launch(void* const* d_in, const int* in_sizes, int n_in,
                              void* d_out, int out_size) {
    const float* x     = (const float*)d_in[0];
    const float* gw    = (const float*)d_in[1];
    const float* w_in  = (const float*)d_in[2];
    const float* w_out = (const float*)d_in[3];
    const float* bias  = (const float*)d_in[4];
    (void)in_sizes; (void)n_in; (void)out_size;

    float* out    = (float*)d_out;
    float* logits = out + (size_t)NTOK * HDIM;

    cudaFuncSetAttribute(gemm_tc<0, HDIM / 64>,
                         cudaFuncAttributeMaxDynamicSharedMemorySize, SMEM_BYTES);
    cudaFuncSetAttribute(gemm_tc<1, IDIM / 64>,
                         cudaFuncAttributeMaxDynamicSharedMemorySize, SMEM_BYTES);

    zero_kernel<<<1, 32>>>();
    router_kernel<<<NTOK / 8, 256>>>(x, gw, logits);
    offsets_kernel<<<1, 32>>>();
    assign_kernel<<<NTOK / 256, 256>>>();
    gemm_tc<0, HDIM / 64><<<dim3(NEXP * 32, IDIM / BN), 256, SMEM_BYTES>>>(x, w_in);
    gemm_tc<1, IDIM / 64><<<dim3(NEXP * 32, HDIM / BN), 256, SMEM_BYTES>>>(x, w_out);
    combine_kernel<<<(NTOK * (HDIM / 4)) / 256, 256>>>(bias, out);
}

// round 10
// speedup vs baseline: 3.6881x; 1.2793x over previous
#include <cuda_runtime.h>
#include <cuda_bf16.h>
#include <math.h>
#include <cstdint>

// ---------------------------------------------------------------------------
// SparseMoE top-2/8, T=4096, H=2048, I=8192, fp32 in/out.
// tcgen05 split-bf16 (hi+lo, 3-pass) GEMMs with ALL fp32->bf16 conversion
// hoisted into prep kernels (weights pre-swizzled into SMEM-image tiles).
// FFMA2 SIMT fallback kept for the plain-sm_103 compile pass.
// d_out layout: [out (T*H) | router_logits (T*E)], f32.
// ---------------------------------------------------------------------------

#if defined(__CUDA_ARCH__) && (defined(__CUDA_ARCH_FEAT_SM103_ALL) || \
    defined(__CUDA_ARCH_SPECIFIC__) || defined(__CUDA_ARCH_FAMILY_SPECIFIC__))
#define TC_ON 1
#else
#define TC_ON 0
#endif

#define HDIM 2048
#define IDIM 8192
#define NEXP 8
#define NTOK 4096
#define NPAIR (NTOK * 2)
#define BM 128
#define BN 128

// -------------------- device scratch ---------------------------------------
__device__ int   g_count[NEXP];
__device__ int   g_off[NEXP];
__device__ int   g_cursor[NEXP];
__device__ int   g_topk_e[NPAIR];
__device__ float g_topk_w[NPAIR];
__device__ int   g_rowtok[NPAIR];
__device__ float g_roww[NPAIR];
__device__ int   g_pairpos[NPAIR];
__device__ float g_ypart[(size_t)NPAIR * HDIM];              // 67 MB

__device__ __nv_bfloat16 g_x_hi[(size_t)NTOK * HDIM];        // 16.8 MB
__device__ __nv_bfloat16 g_x_lo[(size_t)NTOK * HDIM];
__device__ __nv_bfloat16 g_hmid_hi[(size_t)NPAIR * IDIM];    // 134 MB
__device__ __nv_bfloat16 g_hmid_lo[(size_t)NPAIR * IDIM];
// Pre-swizzled weight tiles: per (e, tn, kb): 16KB hi tile + 16KB lo tile.
__device__ unsigned char g_win_t[(size_t)NEXP * 64 * 32 * 2 * 16384];   // 512 MB
__device__ unsigned char g_wout_t[(size_t)NEXP * 16 * 128 * 2 * 16384]; // 512 MB

// -------------------- generic helpers --------------------------------------
__device__ __forceinline__ uint32_t smem_to_u32(const void* p) {
    uint32_t a;
    asm("{ .reg .u64 t; cvta.to.shared.u64 t, %1; cvt.u32.u64 %0, t; }"
        : "=r"(a) : "l"(p));
    return a;
}
__device__ __forceinline__ unsigned sw128(unsigned off) {
    return off ^ ((off >> 3) & 0x70);
}

__device__ __forceinline__ void cvt4(float4 v, uint2& h, uint2& l) {
    __nv_bfloat162 h0 = __floats2bfloat162_rn(v.x, v.y);
    __nv_bfloat162 h1 = __floats2bfloat162_rn(v.z, v.w);
    float2 f0 = __bfloat1622float2(h0);
    float2 f1 = __bfloat1622float2(h1);
    __nv_bfloat162 l0 = __floats2bfloat162_rn(v.x - f0.x, v.y - f0.y);
    __nv_bfloat162 l1 = __floats2bfloat162_rn(v.z - f1.x, v.w - f1.y);
    h.x = *(unsigned*)&h0; h.y = *(unsigned*)&h1;
    l.x = *(unsigned*)&l0; l.y = *(unsigned*)&l1;
}

// f32x2 packed-FMA helpers (fallback path)
__device__ __forceinline__ unsigned long long pack2(float lo, float hi) {
    unsigned long long r;
    asm("mov.b64 %0, {%1, %2};" : "=l"(r) : "f"(lo), "f"(hi));
    return r;
}
__device__ __forceinline__ void unpack2(unsigned long long v, float &lo, float &hi) {
    asm("mov.b64 {%0, %1}, %2;" : "=f"(lo), "=f"(hi) : "l"(v));
}
__device__ __forceinline__ void ffma2(unsigned long long &c,
                                      unsigned long long a,
                                      unsigned long long b) {
    asm("fma.rn.f32x2 %0, %1, %2, %3;" : "=l"(c) : "l"(a), "l"(b), "l"(c));
}

// -------------------- tcgen05 PTX (guarded) --------------------------------
#if TC_ON
__device__ __forceinline__ uint32_t elect_one_pred() {
    uint32_t pred;
    asm volatile(
        "{\n\t.reg .pred p;\n\t"
        "elect.sync _|p, 0xFFFFFFFF;\n\t"
        "selp.b32 %0, 1, 0, p;\n\t}"
        : "=r"(pred));
    return pred;
}

#define MBARRIER_INIT(addr, count) \
    asm volatile("mbarrier.init.shared.b64 [%0], %1;" \
                 :: "r"((uint32_t)(addr)), "r"((uint32_t)(count)) : "memory")

#define MBARRIER_WAIT_PARITY(mbar_smem_addr, phase_parity) do { \
    uint32_t _mbar = (uint32_t)(mbar_smem_addr); \
    uint32_t _parity = (uint32_t)(phase_parity); \
    uint32_t _done; \
    asm volatile( \
        "{\n\t.reg .pred p;\n\t" \
        "mbarrier.try_wait.parity.acquire.cta.shared::cta.b64 p, [%1], %2;\n\t" \
        "selp.b32 %0, 1, 0, p;\n\t}" \
        : "=r"(_done) : "r"(_mbar), "r"(_parity) : "memory"); \
    if (!_done) { \
        asm volatile( \
            "{\n\t.reg .pred P1;\n\t" \
            "WAIT_LOOP_%=:\n\t" \
            "mbarrier.try_wait.parity.acquire.cta.shared::cta.b64 P1, [%0], %1, 0x989680;\n\t" \
            "@P1 bra.uni WAIT_DONE_%=;\n\t" \
            "bra.uni WAIT_LOOP_%=;\n\t" \
            "WAIT_DONE_%=:\n\t}" \
            :: "r"(_mbar), "r"(_parity) : "memory"); \
    } \
} while (0)

#define TCGEN05_ALLOC(smem_result_addr, nCols) \
    asm volatile("tcgen05.alloc.cta_group::1.sync.aligned.shared::cta.b32 [%0], %1;" \
                 :: "r"((uint32_t)(smem_result_addr)), "r"((uint32_t)(nCols)) : "memory")
#define TCGEN05_DEALLOC(tmem_addr, nCols) \
    asm volatile("tcgen05.dealloc.cta_group::1.sync.aligned.b32 %0, %1;" \
                 :: "r"(tmem_addr), "r"((uint32_t)(nCols)))
#define TCGEN05_RELINQUISH() \
    asm volatile("tcgen05.relinquish_alloc_permit.cta_group::1.sync.aligned;")
#define TCGEN05_COMMIT(mbar) \
    asm volatile("tcgen05.commit.cta_group::1.mbarrier::arrive::one.shared::cluster.b64 [%0];" \
                 :: "r"((uint32_t)(mbar)) : "memory")
#define TCGEN05_FENCE_AFTER() \
    asm volatile("tcgen05.fence::after_thread_sync;" ::: "memory")
#define TCGEN05_FENCE_BEFORE() \
    asm volatile("tcgen05.fence::before_thread_sync;" ::: "memory")
#define TCGEN05_WAIT_LD() \
    asm volatile("tcgen05.wait::ld.sync.aligned;" ::: "memory")

#define TCGEN05_LD_32X32B_X32(r, tmem_addr) \
    asm volatile( \
        "tcgen05.ld.sync.aligned.32x32b.x32.b32 " \
        "{%0, %1, %2, %3, %4, %5, %6, %7, " \
        " %8, %9, %10, %11, %12, %13, %14, %15, " \
        " %16, %17, %18, %19, %20, %21, %22, %23, " \
        " %24, %25, %26, %27, %28, %29, %30, %31}, [%32];" \
        : "=r"((r)[0]),  "=r"((r)[1]),  "=r"((r)[2]),  "=r"((r)[3]), \
          "=r"((r)[4]),  "=r"((r)[5]),  "=r"((r)[6]),  "=r"((r)[7]), \
          "=r"((r)[8]),  "=r"((r)[9]),  "=r"((r)[10]), "=r"((r)[11]), \
          "=r"((r)[12]), "=r"((r)[13]), "=r"((r)[14]), "=r"((r)[15]), \
          "=r"((r)[16]), "=r"((r)[17]), "=r"((r)[18]), "=r"((r)[19]), \
          "=r"((r)[20]), "=r"((r)[21]), "=r"((r)[22]), "=r"((r)[23]), \
          "=r"((r)[24]), "=r"((r)[25]), "=r"((r)[26]), "=r"((r)[27]), \
          "=r"((r)[28]), "=r"((r)[29]), "=r"((r)[30]), "=r"((r)[31]) \
        : "r"(tmem_addr))

__device__ __forceinline__ void mma_ss(uint32_t d, uint64_t a, uint64_t b,
                                       uint32_t idesc, bool accum) {
    uint32_t en = accum ? 1u : 0u;
    asm volatile(
        "{\n\t.reg .pred p;\n\t"
        "setp.ne.u32 p, %5, 0;\n\t"
        "tcgen05.mma.cta_group::1.kind::f16 [%0], %1, %2, %3, {%4, %4, %4, %4}, p;\n\t}"
        :: "r"(d), "l"(a), "l"(b), "r"(idesc), "r"(0u), "r"(en)
        : "memory");
}
#endif  // TC_ON

static constexpr uint64_t SMEM_DESC_BASE_SW128 =
    (uint64_t(2) << 61) | (uint64_t(1) << 46) | (uint64_t(64) << 32) | (uint64_t(1) << 16);
#define MAKE_SMEM_DESC(base_addr) \
    (SMEM_DESC_BASE_SW128 | ((uint64_t)((base_addr) >> 4) & 0x3FFF))

// idesc: dtype=F32(1<<4), atype=BF16(1<<7), btype=BF16(1<<10), N/8<<17, M/16<<24
#define GEMM_IDESC 0x8200490u   // M=128, N=128

// -------------------- SMEM layout (tcgen05 path) ---------------------------
// Per buffer: A hi 16KB | A lo 16KB | B hi 16KB | B lo 16KB = 64KB; double-buf.
#define SM_A(b)  (1024 + (b) * 65536)
#define SM_B(b)  (SM_A(b) + 32768)
#define SMEM_BYTES 132096

// -------------------- small kernels ----------------------------------------
__global__ void zero_kernel() {
    int t = threadIdx.x;
    if (t < NEXP) { g_count[t] = 0; g_cursor[t] = 0; }
}

__global__ void router_kernel(const float* __restrict__ x,
                              const float* __restrict__ gw,
                              float* __restrict__ logits_out) {
    int warp = (blockIdx.x * blockDim.x + threadIdx.x) >> 5;
    int lane = threadIdx.x & 31;
    if (warp >= NTOK) return;
    const float* xr = x + (size_t)warp * HDIM;

    float acc[NEXP];
#pragma unroll
    for (int e = 0; e < NEXP; ++e) acc[e] = 0.f;
    for (int h = lane; h < HDIM; h += 32) {
        float xv = xr[h];
        float4 g0 = *(const float4*)(gw + (size_t)h * NEXP);
        float4 g1 = *(const float4*)(gw + (size_t)h * NEXP + 4);
        acc[0] += xv * g0.x; acc[1] += xv * g0.y;
        acc[2] += xv * g0.z; acc[3] += xv * g0.w;
        acc[4] += xv * g1.x; acc[5] += xv * g1.y;
        acc[6] += xv * g1.z; acc[7] += xv * g1.w;
    }
#pragma unroll
    for (int e = 0; e < NEXP; ++e)
#pragma unroll
        for (int o = 16; o > 0; o >>= 1)
            acc[e] += __shfl_xor_sync(0xffffffffu, acc[e], o);

    if (lane == 0) {
        *(float4*)(logits_out + (size_t)warp * NEXP) =
            make_float4(acc[0], acc[1], acc[2], acc[3]);
        *(float4*)(logits_out + (size_t)warp * NEXP + 4) =
            make_float4(acc[4], acc[5], acc[6], acc[7]);
        int i0 = 0;
#pragma unroll
        for (int e = 1; e < NEXP; ++e) if (acc[e] > acc[i0]) i0 = e;
        int i1 = (i0 == 0) ? 1 : 0;
#pragma unroll
        for (int e = 0; e < NEXP; ++e)
            if (e != i0 && acc[e] > acc[i1]) i1 = e;
        float m  = fmaxf(acc[i0], acc[i1]);
        float e0 = expf(acc[i0] - m);
        float e1 = expf(acc[i1] - m);
        float inv = 1.f / (e0 + e1);
        g_topk_e[warp * 2]     = i0;
        g_topk_e[warp * 2 + 1] = i1;
        g_topk_w[warp * 2]     = e0 * inv;
        g_topk_w[warp * 2 + 1] = e1 * inv;
        atomicAdd(&g_count[i0], 1);
        atomicAdd(&g_count[i1], 1);
    }
}

__global__ void offsets_kernel() {
    if (threadIdx.x == 0) {
        int s = 0;
#pragma unroll
        for (int e = 0; e < NEXP; ++e) { g_off[e] = s; s += g_count[e]; }
    }
}

__global__ void assign_kernel() {
    int t = blockIdx.x * blockDim.x + threadIdx.x;
    if (t >= NTOK) return;
#pragma unroll
    for (int k = 0; k < 2; ++k) {
        int e = g_topk_e[t * 2 + k];
        int slot = atomicAdd(&g_cursor[e], 1);
        int row = g_off[e] + slot;
        g_rowtok[row] = t;
        g_roww[row]   = g_topk_w[t * 2 + k];
        g_pairpos[t * 2 + k] = row;
    }
}

// -------------------- prep: x -> bf16 hi/lo planes -------------------------
__global__ void xprep_kernel(const float* __restrict__ x) {
    size_t i = ((size_t)blockIdx.x * blockDim.x + threadIdx.x) * 4;
    float4 v = *(const float4*)(x + i);
    uint2 h, l;
    cvt4(v, h, l);
    *(uint2*)((char*)g_x_hi + i * 2) = h;
    *(uint2*)((char*)g_x_lo + i * 2) = l;
}

// -------------------- prep: weights -> pre-swizzled hi/lo tiles ------------
// Tile (e, tn, kb): 128 N-rows x 64 K-cols bf16, SW128, tile[n][k] = w[e][kb*64+k][tn*128+n].
// dst offset = ((e*NTN + tn)*KB + kb) * 32768  { +0 hi, +16384 lo }.
__global__ void wprep_kernel(const float* __restrict__ src,
                             unsigned char* __restrict__ dst,
                             int KB, int ldb) {
    int tn = blockIdx.x, kb = blockIdx.y, e = blockIdx.z;
    int NTN = gridDim.x;
    int t = threadIdx.x;
    int n = t & 127;
    int plane = t >> 7;   // 0 = hi, 1 = lo
    const float* s = src + (size_t)e * (size_t)(KB * 64) * ldb
                   + (size_t)kb * 64 * ldb + (size_t)tn * 128 + n;
    unsigned char* d = dst + (((size_t)(e * NTN + tn) * KB + kb) * 2 + plane) * 16384;

#pragma unroll
    for (int half = 0; half < 2; ++half) {
        float v[32];
#pragma unroll
        for (int k = 0; k < 32; ++k)
            v[k] = s[(size_t)(half * 32 + k) * ldb];
        unsigned out[16];
#pragma unroll
        for (int p = 0; p < 16; ++p) {
            float a = v[2 * p], b = v[2 * p + 1];
            __nv_bfloat162 hh = __floats2bfloat162_rn(a, b);
            if (plane) {
                float2 hf = __bfloat1622float2(hh);
                hh = __floats2bfloat162_rn(a - hf.x, b - hf.y);
            }
            out[p] = *(unsigned*)&hh;
        }
#pragma unroll
        for (int q = 0; q < 4; ++q) {
            unsigned so = sw128((unsigned)(n * 128 + half * 64 + q * 16));
            *(uint4*)(d + so) = ((uint4*)out)[q];
        }
    }
}

// -------------------- grouped GEMM -----------------------------------------
// MODE 0: hmid(hi/lo planes) = gelu(gather(x planes) @ win_tiles), K=HDIM
// MODE 1: ypart(f32) = roww * (hmid planes @ wout_tiles),          K=IDIM
template <int MODE, int KT64>
__global__ __launch_bounds__(256, 1)
void gemm_tc(const float* __restrict__ Braw) {
    const int e   = blockIdx.x >> 5;
    const int tm  = blockIdx.x & 31;
    const int cnt = g_count[e];
    if (tm * BM >= cnt) return;
    const int tn   = blockIdx.y;
    const int row0 = g_off[e] + tm * BM;
    const int ldb  = (MODE == 0) ? IDIM : HDIM;
    const int NTN  = (MODE == 0) ? 64 : 16;
    const int lda  = (MODE == 0) ? HDIM : IDIM;

    extern __shared__ char smem[];
    const int tid  = threadIdx.x;
    const int wid  = tid >> 5;
    const int lane = tid & 31;

    const unsigned char* BT =
        (MODE == 0 ? g_win_t : g_wout_t) + (size_t)(e * NTN + tn) * KT64 * 32768;

#if TC_ON
    // ======================= tcgen05 split-bf16 path =======================
    uint32_t smem_base = smem_to_u32(smem);
    if (wid == 0) TCGEN05_ALLOC(smem_base, 128);
    if (tid == 0) {
        MBARRIER_INIT(smem_base + 16, 1);
        MBARRIER_INIT(smem_base + 24, 1);
    }
    __syncthreads();
    uint32_t tmem;
    asm volatile("ld.shared.b32 %0, [%1];" : "=r"(tmem) : "r"(smem_base));

    // A loader mapping: 2 threads per row
    const int ar = tid >> 1;
    const int ah = tid & 1;
    int arow_idx;
    if (MODE == 0)
        arow_idx = ((tm * BM + ar) < cnt) ? g_rowtok[row0 + ar] : g_rowtok[row0];
    else
        arow_idx = ((tm * BM + ar) < cnt) ? (row0 + ar) : row0;
    const __nv_bfloat16* AhiRow =
        (MODE == 0 ? g_x_hi : g_hmid_hi) + (size_t)arow_idx * lda;
    const __nv_bfloat16* AloRow =
        (MODE == 0 ? g_x_lo : g_hmid_lo) + (size_t)arow_idx * lda;

    auto load_block = [&](int kb, int buf) {
        // B: linear coalesced copy of pre-swizzled 32KB (hi+lo)
        const uint4* bs = (const uint4*)(BT + (size_t)kb * 32768);
        uint4* bd = (uint4*)(smem + SM_B(buf));
#pragma unroll
        for (int i = 0; i < 8; ++i) bd[i * 256 + tid] = bs[i * 256 + tid];
        // A: 64B per plane per thread, swizzled store
        const uint4* ahp = (const uint4*)(AhiRow + kb * 64 + ah * 32);
        const uint4* alp = (const uint4*)(AloRow + kb * 64 + ah * 32);
        char* ad = smem + SM_A(buf);
#pragma unroll
        for (int i = 0; i < 4; ++i) {
            unsigned so = sw128((unsigned)(ar * 128 + ah * 64 + i * 16));
            *(uint4*)(ad + so) = ahp[i];
            *(uint4*)(ad + 16384 + so) = alp[i];
        }
    };

    load_block(0, 0);
    __syncthreads();

    for (int kb = 0; kb < KT64; ++kb) {
        int buf = kb & 1;
        if (wid == 0 && elect_one_pred()) {
            asm volatile("fence.proxy.async.shared::cta;" ::: "memory");
            uint64_t dA  = MAKE_SMEM_DESC(smem_base + SM_A(buf));
            uint64_t dB  = MAKE_SMEM_DESC(smem_base + SM_B(buf));
            uint64_t dAl = dA + 1024;   // +16KB in 16B units
            uint64_t dBl = dB + 1024;
#pragma unroll
            for (int s = 0; s < 4; ++s)
                mma_ss(tmem, dA + s * 2, dB + s * 2, GEMM_IDESC, !(kb == 0 && s == 0));
#pragma unroll
            for (int s = 0; s < 4; ++s)
                mma_ss(tmem, dA + s * 2, dBl + s * 2, GEMM_IDESC, true);
#pragma unroll
            for (int s = 0; s < 4; ++s)
                mma_ss(tmem, dAl + s * 2, dB + s * 2, GEMM_IDESC, true);
            TCGEN05_COMMIT(smem_base + 16 + buf * 8);
        }
        if (kb + 1 < KT64) {
            int nbuf = buf ^ 1;
            if (kb >= 1)
                MBARRIER_WAIT_PARITY(smem_base + 16 + nbuf * 8, ((kb - 1) >> 1) & 1);
            load_block(kb + 1, nbuf);
        }
        __syncthreads();
    }
    MBARRIER_WAIT_PARITY(smem_base + 16 + ((KT64 - 1) & 1) * 8, ((KT64 - 1) >> 1) & 1);
    TCGEN05_FENCE_AFTER();

    // epilogue
    if (wid < 4) {
        int m = wid * 32 + lane;
        bool valid = (tm * BM + m) < cnt;
        int grow = row0 + m;
        float wscale = 1.f;
        if (MODE == 1) wscale = valid ? g_roww[grow] : 0.f;
#pragma unroll
        for (int nb = 0; nb < 4; ++nb) {
            uint32_t dr[32];
            TCGEN05_LD_32X32B_X32(dr, tmem + nb * 32);
            TCGEN05_WAIT_LD();
            if (valid) {
                float f[32];
#pragma unroll
                for (int j = 0; j < 32; ++j) f[j] = __uint_as_float(dr[j]);
                if (MODE == 0) {
#pragma unroll
                    for (int j = 0; j < 32; ++j) {
                        float t = f[j];
                        f[j] = 0.5f * t * (1.0f + erff(t * 0.7071067811865476f));
                    }
                    // write hi/lo bf16 planes
                    unsigned oh[16], ol[16];
#pragma unroll
                    for (int p = 0; p < 16; ++p) {
                        float a = f[2 * p], b = f[2 * p + 1];
                        __nv_bfloat162 hh = __floats2bfloat162_rn(a, b);
                        float2 hf = __bfloat1622float2(hh);
                        __nv_bfloat162 ll = __floats2bfloat162_rn(a - hf.x, b - hf.y);
                        oh[p] = *(unsigned*)&hh;
                        ol[p] = *(unsigned*)&ll;
                    }
                    size_t off = (size_t)grow * IDIM + (size_t)tn * BN + nb * 32;
#pragma unroll
                    for (int q = 0; q < 4; ++q) {
                        *(uint4*)((char*)g_hmid_hi + off * 2 + q * 16) = ((uint4*)oh)[q];
                        *(uint4*)((char*)g_hmid_lo + off * 2 + q * 16) = ((uint4*)ol)[q];
                    }
                } else {
#pragma unroll
                    for (int j = 0; j < 32; ++j) f[j] *= wscale;
                    float* dst = g_ypart + (size_t)grow * HDIM + (size_t)tn * BN + nb * 32;
#pragma unroll
                    for (int q = 0; q < 8; ++q)
                        *(float4*)(dst + 4 * q) =
                            make_float4(f[4 * q], f[4 * q + 1], f[4 * q + 2], f[4 * q + 3]);
                }
            }
        }
        TCGEN05_FENCE_BEFORE();
    }
    __syncthreads();
    if (wid == 0) {
        TCGEN05_RELINQUISH();
        TCGEN05_DEALLOC(tmem, 128);
    }

#else
    // ================= FFMA2 SIMT fallback (compiles on plain sm_103) ======
    (void)lane; (void)wid; (void)BT;
    const int KT16 = KT64 * 4;
    float* As = (float*)smem;                       // [2][16][128]
    float* Bs = As + 2 * 16 * 128;

    const int am  = tid & 127;
    const int akq = (tid >> 7) << 3;
    const bool avalid = (tm * BM + am) < cnt;
    int arow_idx;
    if (MODE == 0)
        arow_idx = avalid ? g_rowtok[row0 + am] : g_rowtok[row0];
    else
        arow_idx = avalid ? (row0 + am) : row0;
    const __nv_bfloat16* AhiRow =
        (MODE == 0 ? g_x_hi : g_hmid_hi) + (size_t)arow_idx * lda + akq;
    const __nv_bfloat16* AloRow =
        (MODE == 0 ? g_x_lo : g_hmid_lo) + (size_t)arow_idx * lda + akq;

    const float* Bbase = Braw + (size_t)e * (size_t)KT64 * 64 * ldb + (size_t)tn * BN;
    const int bk = tid >> 4;
    const int bn = (tid & 15) << 3;
    const float* Bp = Bbase + (size_t)bk * ldb + bn;
    const int m0 = (tid >> 4) << 3;
    const int n0 = (tid & 15) << 3;

    unsigned long long acc[8][4];
#pragma unroll
    for (int i = 0; i < 8; ++i)
#pragma unroll
        for (int j = 0; j < 4; ++j) acc[i][j] = 0ull;

    auto loadA8 = [&](int k0, float* out8) {
        uint4 h = *(const uint4*)(AhiRow + k0);
        uint4 l = *(const uint4*)(AloRow + k0);
        const __nv_bfloat162* hp = (const __nv_bfloat162*)&h;
        const __nv_bfloat162* lp = (const __nv_bfloat162*)&l;
#pragma unroll
        for (int p = 0; p < 4; ++p) {
            float2 hf = __bfloat1622float2(hp[p]);
            float2 lf = __bfloat1622float2(lp[p]);
            out8[2 * p] = hf.x + lf.x;
            out8[2 * p + 1] = hf.y + lf.y;
        }
    };

    {
        float a8[8];
        loadA8(0, a8);
#pragma unroll
        for (int q = 0; q < 8; ++q) As[(akq + q) * 128 + am] = a8[q];
        *(float4*)&Bs[bk * 128 + bn]     = *(const float4*)(Bp);
        *(float4*)&Bs[bk * 128 + bn + 4] = *(const float4*)(Bp + 4);
    }
    __syncthreads();

    int buf = 0;
    for (int kt = 0; kt < KT16; ++kt) {
        float na8[8]; float4 nb0, nb1;
        if (kt + 1 < KT16) {
            int k0 = (kt + 1) * 16;
            loadA8(k0, na8);
            nb0 = *(const float4*)(Bp + (size_t)k0 * ldb);
            nb1 = *(const float4*)(Bp + (size_t)k0 * ldb + 4);
        }
        const float* Ab = As + buf * 16 * 128;
        const float* Bb = Bs + buf * 16 * 128;
#pragma unroll
        for (int kk = 0; kk < 16; ++kk) {
            float a8[8];
            *(float4*)&a8[0] = *(const float4*)&Ab[kk * 128 + m0];
            *(float4*)&a8[4] = *(const float4*)&Ab[kk * 128 + m0 + 4];
            ulonglong2 bb0 = *(const ulonglong2*)&Bb[kk * 128 + n0];
            ulonglong2 bb1 = *(const ulonglong2*)&Bb[kk * 128 + n0 + 4];
            unsigned long long b2[4] = {bb0.x, bb0.y, bb1.x, bb1.y};
#pragma unroll
            for (int i = 0; i < 8; ++i) {
                unsigned long long a2 = pack2(a8[i], a8[i]);
#pragma unroll
                for (int j = 0; j < 4; ++j) ffma2(acc[i][j], a2, b2[j]);
            }
        }
        if (kt + 1 < KT16) {
            int nb2 = buf ^ 1;
            float* An = As + nb2 * 16 * 128;
#pragma unroll
            for (int q = 0; q < 8; ++q) An[(akq + q) * 128 + am] = na8[q];
            float* Bn = Bs + nb2 * 16 * 128;
            *(float4*)&Bn[bk * 128 + bn]     = nb0;
            *(float4*)&Bn[bk * 128 + bn + 4] = nb1;
            __syncthreads();
            buf = nb2;
        }
    }

#pragma unroll
    for (int i = 0; i < 8; ++i) {
        int r = tm * BM + m0 + i;
        if (r < cnt) {
            int grow = row0 + m0 + i;
            float v[8];
#pragma unroll
            for (int j = 0; j < 4; ++j) unpack2(acc[i][j], v[2 * j], v[2 * j + 1]);
            if (MODE == 0) {
#pragma unroll
                for (int k = 0; k < 8; ++k) {
                    float t = v[k];
                    v[k] = 0.5f * t * (1.0f + erff(t * 0.7071067811865476f));
                }
                size_t off = (size_t)grow * IDIM + (size_t)tn * BN + n0;
#pragma unroll
                for (int p = 0; p < 4; ++p) {
                    float a = v[2 * p], b = v[2 * p + 1];
                    __nv_bfloat162 hh = __floats2bfloat162_rn(a, b);
                    float2 hf = __bfloat1622float2(hh);
                    __nv_bfloat162 ll = __floats2bfloat162_rn(a - hf.x, b - hf.y);
                    *(unsigned*)((char*)g_hmid_hi + (off + 2 * p) * 2) = *(unsigned*)&hh;
                    *(unsigned*)((char*)g_hmid_lo + (off + 2 * p) * 2) = *(unsigned*)&ll;
                }
            } else {
                float w = g_roww[grow];
#pragma unroll
                for (int k = 0; k < 8; ++k) v[k] *= w;
                float* dst = g_ypart + (size_t)grow * HDIM + (size_t)tn * BN + n0;
                *(float4*)(dst)     = make_float4(v[0], v[1], v[2], v[3]);
                *(float4*)(dst + 4) = make_float4(v[4], v[5], v[6], v[7]);
            }
        }
    }
#endif  // TC_ON
}

// -------------------- combine ----------------------------------------------
__global__ void combine_kernel(const float* __restrict__ bias,
                               float* __restrict__ out) {
    int idx = blockIdx.x * blockDim.x + threadIdx.x;
    if (idx >= NTOK * (HDIM / 4)) return;
    int t  = idx >> 9;
    int c4 = (idx & 511) << 2;
    int p0 = g_pairpos[t * 2];
    int p1 = g_pairpos[t * 2 + 1];
    float4 bv = *(const float4*)(bias + c4);
    float4 y0 = *(const float4*)(g_ypart + (size_t)p0 * HDIM + c4);
    float4 y1 = *(const float4*)(g_ypart + (size_t)p1 * HDIM + c4);
    float4 o;
    o.x = bv.x + y0.x + y1.x;
    o.y = bv.y + y0.y + y1.y;
    o.z = bv.z + y0.z + y1.z;
    o.w = bv.w + y0.w + y1.w;
    *(float4*)(out + (size_t)t * HDIM + c4) = o;
}

// ---------------------------------------------------------------------------
extern "C" void kernel_launch(void* const* d_in, const int* in_sizes, int n_in,
                              void* d_out, int out_size) {
    const float* x     = (const float*)d_in[0];
    const float* gw    = (const float*)d_in[1];
    const float* w_in  = (const float*)d_in[2];
    const float* w_out = (const float*)d_in[3];
    const float* bias  = (const float*)d_in[4];
    (void)in_sizes; (void)n_in; (void)out_size;

    float* out    = (float*)d_out;
    float* logits = out + (size_t)NTOK * HDIM;

    unsigned char* win_t;
    unsigned char* wout_t;
    cudaGetSymbolAddress((void**)&win_t, g_win_t);
    cudaGetSymbolAddress((void**)&wout_t, g_wout_t);

    cudaFuncSetAttribute(gemm_tc<0, HDIM / 64>,
                         cudaFuncAttributeMaxDynamicSharedMemorySize, SMEM_BYTES);
    cudaFuncSetAttribute(gemm_tc<1, IDIM / 64>,
                         cudaFuncAttributeMaxDynamicSharedMemorySize, SMEM_BYTES);

    zero_kernel<<<1, 32>>>();
    router_kernel<<<NTOK / 8, 256>>>(x, gw, logits);
    offsets_kernel<<<1, 32>>>();
    assign_kernel<<<NTOK / 256, 256>>>();
    xprep_kernel<<<(NTOK * HDIM) / (256 * 4), 256>>>(x);
    wprep_kernel<<<dim3(64, 32, NEXP), 256>>>(w_in, win_t, 32, IDIM);
    wprep_kernel<<<dim3(16, 128, NEXP), 256>>>(w_out, wout_t, 128, HDIM);
    gemm_tc<0, HDIM / 64><<<dim3(NEXP * 32, IDIM / BN), 256, SMEM_BYTES>>>(w_in);
    gemm_tc<1, IDIM / 64><<<dim3(NEXP * 32, HDIM / BN), 256, SMEM_BYTES>>>(w_out);
    combine_kernel<<<(NTOK * (HDIM / 4)) / 256, 256>>>(bias, out);
}